// round 2
// baseline (speedup 1.0000x reference)
#include <cuda_runtime.h>
#include <math.h>

// Problem constants
#define WE    300      // word-embedding dim
#define RVLD  320      // padded row length for rvT (1280B, 128-aligned)
#define DE    256      // doc-embedding dim
#define NV    50000    // vocab
#define ND    100000   // docs
#define NB    4096     // batch
#define NGW   10       // words per bag
#define NZ    10       // negatives
#define KP    320      // padded K for GEMM (300 -> 320, zero fill)

#define BM 64
#define BN 64
#define BK 32

// ---- device scratch (static allocation; no runtime mallocs) ----
__device__ float  d_rvT[NV * RVLD];        // 64 MB   rv transposed (v-major rows)
__device__ float  d_rdT[ND * DE];          // 102 MB  rd transposed (doc-major rows)
__device__ float  d_normedT[NB * KP];      // 5 MB    normalized g, (b, we) rows, zero-padded
__device__ float  d_projP[DE * KP];        // 0.3 MB  proj padded to KP
__device__ float  d_tpreT[NB * DE];        // 4 MB    t_pre transposed (b, de)
__device__ double d_sum[DE];
__device__ double d_sumsq[DE];
__device__ double d_rdsq;
__device__ double d_projsq;
__device__ double d_loss;
__device__ unsigned int d_count;

__device__ __forceinline__ float warp_sum(float v) {
    #pragma unroll
    for (int o = 16; o > 0; o >>= 1) v += __shfl_xor_sync(0xffffffffu, v, o);
    return v;
}

// ---- K0: zero accumulators ----
__global__ void k_init() {
    int t = threadIdx.x;
    if (t < DE) { d_sum[t] = 0.0; d_sumsq[t] = 0.0; }
    if (t == 256) d_rdsq = 0.0;
    if (t == 257) d_projsq = 0.0;
    if (t == 258) d_loss = 0.0;
    if (t == 259) d_count = 0u;
}

// ---- K1: transpose rd (256 x 100000) -> rdT (100000 x 256), fused sum(rd^2) ----
__global__ __launch_bounds__(256) void k_rd_T(const float* __restrict__ rd) {
    __shared__ float tile[32][33];
    int tx = threadIdx.x, ty = threadIdx.y;
    int x  = blockIdx.x * 32 + tx;    // doc
    int y0 = blockIdx.y * 32;         // de
    float ss = 0.f;
    #pragma unroll
    for (int i = 0; i < 32; i += 8) {
        float v = rd[(y0 + ty + i) * ND + x];
        tile[ty + i][tx] = v;
        ss += v * v;
    }
    __syncthreads();
    int xo = y0 + tx;                 // de
    int yo = blockIdx.x * 32;         // doc
    #pragma unroll
    for (int i = 0; i < 32; i += 8)
        d_rdT[(yo + ty + i) * DE + xo] = tile[tx][ty + i];

    ss = warp_sum(ss);
    __shared__ float red[8];
    int tid = ty * 32 + tx;
    if ((tid & 31) == 0) red[tid >> 5] = ss;
    __syncthreads();
    if (tid == 0) {
        float s = 0.f;
        #pragma unroll
        for (int i = 0; i < 8; i++) s += red[i];
        atomicAdd(&d_rdsq, (double)s);
    }
}

// ---- K2: transpose rv (300 x 50000) -> rvT (50000 x 320-padded) ----
__global__ __launch_bounds__(256) void k_rv_T(const float* __restrict__ rv) {
    __shared__ float tile[32][33];
    int tx = threadIdx.x, ty = threadIdx.y;
    int x  = blockIdx.x * 32 + tx;    // v
    int y0 = blockIdx.y * 32;         // we
    #pragma unroll
    for (int i = 0; i < 32; i += 8) {
        int y = y0 + ty + i;
        tile[ty + i][tx] = (y < WE && x < NV) ? rv[y * NV + x] : 0.f;
    }
    __syncthreads();
    int xo = y0 + tx;                 // we
    int y1 = blockIdx.x * 32;         // v
    #pragma unroll
    for (int i = 0; i < 32; i += 8) {
        int y = y1 + ty + i;
        if (y < NV && xo < WE) d_rvT[y * RVLD + xo] = tile[tx][ty + i];
    }
}

// ---- K3: pad proj into projP, fused sum(proj^2) ----
__global__ __launch_bounds__(RVLD) void k_proj_prep(const float* __restrict__ proj) {
    int de = blockIdx.x, t = threadIdx.x;
    float v = (t < WE) ? proj[de * WE + t] : 0.f;
    d_projP[de * KP + t] = v;
    float ss = warp_sum(v * v);
    __shared__ float red[10];
    if ((t & 31) == 0) red[t >> 5] = ss;
    __syncthreads();
    if (t == 0) {
        float s = 0.f;
        #pragma unroll
        for (int i = 0; i < 10; i++) s += red[i];
        atomicAdd(&d_projsq, (double)s);
    }
}

// ---- K4: gather 10 rvT rows per b, sum, L2-normalize (mean /10 cancels) ----
__global__ __launch_bounds__(RVLD) void k_gather(const int* __restrict__ word_ids) {
    int b = blockIdx.x, t = threadIdx.x;
    __shared__ int ids[NGW];
    if (t < NGW) ids[t] = word_ids[b * NGW + t];
    __syncthreads();
    float s = 0.f;
    if (t < WE) {
        #pragma unroll
        for (int g = 0; g < NGW; g++) s += d_rvT[ids[g] * RVLD + t];
    }
    float ss = warp_sum(s * s);
    __shared__ float red[10];
    __shared__ float rn;
    if ((t & 31) == 0) red[t >> 5] = ss;
    __syncthreads();
    if (t == 0) {
        float q = 0.f;
        #pragma unroll
        for (int i = 0; i < 10; i++) q += red[i];
        rn = 1.f / sqrtf(q);
    }
    __syncthreads();
    d_normedT[b * KP + t] = (t < WE) ? s * rn : 0.f;
}

// ---- K5: t_preT[b,de] = sum_we normedT[b,we]*projP[de,we]; fused row Σ/Σ² ----
__global__ __launch_bounds__(256) void k_gemm() {
    __shared__ float As[BM][BK + 1];
    __shared__ float Bs[BN][BK + 1];
    int tid = threadIdx.x;
    int tx = tid & 15, ty = tid >> 4;
    int b0 = blockIdx.x * BM;
    int d0 = blockIdx.y * BN;
    float acc[4][4];
    #pragma unroll
    for (int i = 0; i < 4; i++)
        #pragma unroll
        for (int j = 0; j < 4; j++) acc[i][j] = 0.f;

    for (int k0 = 0; k0 < KP; k0 += BK) {
        #pragma unroll
        for (int l = 0; l < 2; l++) {
            int f = tid + l * 256;
            int r = f >> 3, c = (f & 7) << 2;
            float4 va = *(const float4*)&d_normedT[(b0 + r) * KP + k0 + c];
            As[r][c] = va.x; As[r][c+1] = va.y; As[r][c+2] = va.z; As[r][c+3] = va.w;
            float4 vb = *(const float4*)&d_projP[(d0 + r) * KP + k0 + c];
            Bs[r][c] = vb.x; Bs[r][c+1] = vb.y; Bs[r][c+2] = vb.z; Bs[r][c+3] = vb.w;
        }
        __syncthreads();
        #pragma unroll
        for (int k = 0; k < BK; k++) {
            float a[4], bb[4];
            #pragma unroll
            for (int i = 0; i < 4; i++) a[i] = As[ty * 4 + i][k];
            #pragma unroll
            for (int j = 0; j < 4; j++) bb[j] = Bs[tx * 4 + j][k];
            #pragma unroll
            for (int i = 0; i < 4; i++)
                #pragma unroll
                for (int j = 0; j < 4; j++) acc[i][j] += a[i] * bb[j];
        }
        __syncthreads();
    }

    #pragma unroll
    for (int i = 0; i < 4; i++) {
        float4 o = make_float4(acc[i][0], acc[i][1], acc[i][2], acc[i][3]);
        *(float4*)&d_tpreT[(b0 + ty * 4 + i) * DE + d0 + tx * 4] = o;
    }

    __shared__ float stS[16][64];
    __shared__ float stQ[16][64];
    #pragma unroll
    for (int j = 0; j < 4; j++) {
        float s = 0.f, q = 0.f;
        #pragma unroll
        for (int i = 0; i < 4; i++) { s += acc[i][j]; q += acc[i][j] * acc[i][j]; }
        stS[ty][tx * 4 + j] = s;
        stQ[ty][tx * 4 + j] = q;
    }
    __syncthreads();
    if (tid < 64) {
        float s = 0.f, q = 0.f;
        #pragma unroll
        for (int r = 0; r < 16; r++) { s += stS[r][tid]; q += stQ[r][tid]; }
        atomicAdd(&d_sum[d0 + tid], (double)s);
        atomicAdd(&d_sumsq[d0 + tid], (double)q);
    }
}

// ---- K6: per-b loss; per-thread stats finalize fused in; last block writes out ----
__global__ __launch_bounds__(256) void k_loss(const float* __restrict__ beta,
                                              const int* __restrict__ doc_ids,
                                              const int* __restrict__ neg_ids,
                                              float* __restrict__ out) {
    int b = blockIdx.x, tid = threadIdx.x;
    int w = tid >> 5, lane = tid & 31;
    __shared__ int   nid[NZ];
    __shared__ int   did;
    __shared__ float part[1 + NZ][8];
    if (tid == 0) did = doc_ids[b];
    if (tid < NZ) nid[tid] = neg_ids[b * NZ + tid];

    // per-thread stats finalize (was k_stats): t = (t_pre - mean)/sqrt(std) + beta
    double s = d_sum[tid], q = d_sumsq[tid];
    double mean = s / NB;
    double var = (q - s * mean) / (NB - 1);   // ddof = 1
    if (var < 1e-30) var = 1e-30;
    double rs = 1.0 / sqrt(sqrt(var));        // 1/sqrt(std)

    float t = (float)(((double)d_tpreT[b * DE + tid] - mean) * rs + (double)beta[tid]);
    t = fminf(1.f, fmaxf(-1.f, t));
    __syncthreads();

    {
        float v = warp_sum(t * d_rdT[did * DE + tid]);
        if (!lane) part[0][w] = v;
    }
    #pragma unroll
    for (int z = 0; z < NZ; z++) {
        float v = warp_sum(t * d_rdT[nid[z] * DE + tid]);
        if (!lane) part[1 + z][w] = v;
    }
    __syncthreads();
    if (tid == 0) {
        float sp = 0.f;
        #pragma unroll
        for (int i = 0; i < 8; i++) sp += part[0][i];
        float p  = fminf(1.f / (1.f + expf(-sp)), 0.999f);
        float lp = 10.f * logf(p);
        float nsl = 0.f;
        #pragma unroll
        for (int z = 0; z < NZ; z++) {
            float sn = 0.f;
            #pragma unroll
            for (int i = 0; i < 8; i++) sn += part[1 + z][i];
            float pn = fminf(1.f / (1.f + expf(-sn)), 0.999f);
            nsl += logf(fmaxf(1.f - pn, 0.01f));
        }
        atomicAdd(&d_loss, (double)(0.55f * (lp + nsl)));   // (Z+1)/(2Z) = 0.55
        __threadfence();
        unsigned int r = atomicAdd(&d_count, 1u);
        if (r == NB - 1) {   // last block: finalize scalar (was k_final)
            double total = atomicAdd(&d_loss, 0.0);
            out[0] = (float)(total / NB + (0.01 / (2.0 * NB)) * (d_rdsq + d_projsq));
        }
    }
}

extern "C" void kernel_launch(void* const* d_in, const int* in_sizes, int n_in,
                              void* d_out, int out_size) {
    const float* rv       = (const float*)d_in[0];
    const float* rd       = (const float*)d_in[1];
    const float* proj     = (const float*)d_in[2];
    const float* beta     = (const float*)d_in[3];
    const int*   word_ids = (const int*)d_in[4];
    const int*   doc_ids  = (const int*)d_in[5];
    const int*   neg_ids  = (const int*)d_in[6];
    float* out = (float*)d_out;

    // One-time handle creation (host-side objects; no device memory alloc)
    static cudaStream_t s2 = nullptr;
    static cudaEvent_t  eFork = nullptr, eJoin = nullptr;
    if (s2 == nullptr) {
        cudaStreamCreateWithFlags(&s2, cudaStreamNonBlocking);
        cudaEventCreateWithFlags(&eFork, cudaEventDisableTiming);
        cudaEventCreateWithFlags(&eJoin, cudaEventDisableTiming);
    }

    // Find the stream the harness is capturing (legacy vs per-thread), so the
    // fork/join below lands inside the captured graph. Outside capture -> 0.
    cudaStream_t ms = (cudaStream_t)0;
    cudaStreamCaptureStatus st = cudaStreamCaptureStatusNone;
    cudaStreamGetCaptureInfo(cudaStreamPerThread, &st, nullptr, nullptr, nullptr, nullptr);
    if (st == cudaStreamCaptureStatusActive) {
        ms = cudaStreamPerThread;
    } else {
        st = cudaStreamCaptureStatusNone;
        cudaStreamGetCaptureInfo(cudaStreamLegacy, &st, nullptr, nullptr, nullptr, nullptr);
        if (st == cudaStreamCaptureStatusActive) ms = cudaStreamLegacy;
    }

    k_init<<<1, 512, 0, ms>>>();

    // Fork: rd transpose (+ sum rd^2) runs concurrently with the rv pipeline
    cudaEventRecord(eFork, ms);
    cudaStreamWaitEvent(s2, eFork, 0);
    k_rd_T<<<dim3(ND / 32, DE / 32), dim3(32, 8), 0, s2>>>(rd);
    cudaEventRecord(eJoin, s2);

    // Main pipeline: rv transpose -> gather/normalize -> GEMM(+stats)
    k_rv_T<<<dim3((NV + 31) / 32, (WE + 31) / 32), dim3(32, 8), 0, ms>>>(rv);
    k_proj_prep<<<DE, RVLD, 0, ms>>>(proj);
    k_gather<<<NB, RVLD, 0, ms>>>(word_ids);
    k_gemm<<<dim3(NB / BM, DE / BN), 256, 0, ms>>>();

    // Join: loss needs rdT + d_rdsq
    cudaStreamWaitEvent(ms, eJoin, 0);
    k_loss<<<NB, DE, 0, ms>>>(beta, doc_ids, neg_ids, out);
}

// round 5
// speedup vs baseline: 1.4409x; 1.4409x over previous
#include <cuda_runtime.h>
#include <math.h>

// Problem constants
#define WE    300      // word-embedding dim
#define RVLD  320      // padded row length for rvT (1280B, 128-aligned)
#define DE    256      // doc-embedding dim
#define NV    50000    // vocab
#define ND    100000   // docs
#define NB    4096     // batch
#define NGW   10       // words per bag
#define NZ    10       // negatives
#define KP    320      // padded K for GEMM

#define BM 64
#define BN 64
#define BK 32

// ---- device scratch ----
__device__ float  d_rvT[NV * RVLD];        // 64 MB
__device__ float  d_rdT[ND * DE];          // 102 MB
__device__ float  d_normedT[NB * KP];      // 5 MB
__device__ float  d_projP[DE * KP];        // 0.3 MB
__device__ float  d_tpreT[NB * DE];        // 4 MB
__device__ float  d_projpart[64];
__device__ double d_sum[DE];
__device__ double d_sumsq[DE];
__device__ double d_rdsq;
__device__ double d_projsq;
__device__ double d_loss;
__device__ unsigned int d_count;
__device__ float  d_ca[DE];
__device__ float  d_cb[DE];

__device__ __forceinline__ float warp_sum(float v) {
    #pragma unroll
    for (int o = 16; o > 0; o >>= 1) v += __shfl_xor_sync(0xffffffffu, v, o);
    return v;
}

// ---- K0: zero accumulators ----
__global__ void k_init() {
    int t = threadIdx.x;
    if (t < DE) { d_sum[t] = 0.0; d_sumsq[t] = 0.0; }
    if (t == 256) d_rdsq = 0.0;
    if (t == 257) d_loss = 0.0;
    if (t == 258) d_count = 0u;
}

// ---- K1: transpose rd (256 x 100000) -> rdT (100000 x 256), fused sum(rd^2)
//      64x64 tile, float4 gmem on both sides ----
__global__ __launch_bounds__(256) void k_rd_T(const float* __restrict__ rd) {
    __shared__ float tile[64][65];
    int t = threadIdx.x;
    int x0 = blockIdx.x * 64;          // doc
    int y0 = blockIdx.y * 64;          // de
    int r = t >> 4;                    // 0..15
    int c = (t & 15) << 2;             // 0,4,..,60
    float ss = 0.f;
    #pragma unroll
    for (int i = 0; i < 4; i++) {
        int de = r + 16 * i;
        int doc = x0 + c;
        if (doc < ND) {
            float4 v = *(const float4*)&rd[(size_t)(y0 + de) * ND + doc];
            tile[de][c] = v.x; tile[de][c + 1] = v.y;
            tile[de][c + 2] = v.z; tile[de][c + 3] = v.w;
            ss += v.x * v.x + v.y * v.y + v.z * v.z + v.w * v.w;
        }
    }
    __syncthreads();
    #pragma unroll
    for (int i = 0; i < 4; i++) {
        int dl = r + 16 * i;           // doc local
        int doc = x0 + dl;
        if (doc < ND) {
            float4 o = make_float4(tile[c][dl], tile[c + 1][dl],
                                   tile[c + 2][dl], tile[c + 3][dl]);
            *(float4*)&d_rdT[(size_t)doc * DE + y0 + c] = o;
        }
    }
    // block reduce ss -> d_rdsq
    ss = warp_sum(ss);
    __shared__ float red[8];
    if ((t & 31) == 0) red[t >> 5] = ss;
    __syncthreads();
    if (t == 0) {
        float s = 0.f;
        #pragma unroll
        for (int i = 0; i < 8; i++) s += red[i];
        atomicAdd(&d_rdsq, (double)s);
    }
}

// ---- K2: transpose rv (300 x 50000) -> rvT (50000 x 320, zero-padded) ----
__global__ __launch_bounds__(256) void k_rv_T(const float* __restrict__ rv) {
    __shared__ float tile[64][65];
    int t = threadIdx.x;
    int x0 = blockIdx.x * 64;          // v
    int y0 = blockIdx.y * 64;          // we (0,64,128,192,256)
    int r = t >> 4;
    int c = (t & 15) << 2;
    #pragma unroll
    for (int i = 0; i < 4; i++) {
        int we = y0 + r + 16 * i;
        int x = x0 + c;
        if (x < NV) {
            float4 v = make_float4(0.f, 0.f, 0.f, 0.f);
            if (we < WE) v = *(const float4*)&rv[(size_t)we * NV + x];
            int de = r + 16 * i;
            tile[de][c] = v.x; tile[de][c + 1] = v.y;
            tile[de][c + 2] = v.z; tile[de][c + 3] = v.w;
        }
    }
    __syncthreads();
    #pragma unroll
    for (int i = 0; i < 4; i++) {
        int vl = r + 16 * i;
        int v = x0 + vl;
        if (v < NV) {
            float4 o = make_float4(tile[c][vl], tile[c + 1][vl],
                                   tile[c + 2][vl], tile[c + 3][vl]);
            *(float4*)&d_rvT[(size_t)v * RVLD + y0 + c] = o;
        }
    }
}

// ---- K3: pad proj into projP, per-block partial sum(proj^2) ----
__global__ __launch_bounds__(256) void k_proj_prep(const float* __restrict__ proj) {
    int idx = blockIdx.x * 256 + threadIdx.x;   // over 256*320 outputs
    float ss = 0.f;
    #pragma unroll
    for (int i = 0; i < 5; i++) {
        int o = idx + i * 64 * 256;
        int de = o / KP, cc = o % KP;
        float v = 0.f;
        if (cc < WE) { v = proj[de * WE + cc]; ss += v * v; }
        d_projP[o] = v;
    }
    ss = warp_sum(ss);
    __shared__ float red[8];
    int t = threadIdx.x;
    if ((t & 31) == 0) red[t >> 5] = ss;
    __syncthreads();
    if (t == 0) {
        float s = 0.f;
        #pragma unroll
        for (int i = 0; i < 8; i++) s += red[i];
        d_projpart[blockIdx.x] = s;
    }
}

// ---- K4: gather+normalize, warp-per-batch, float4, no smem ----
__global__ __launch_bounds__(256) void k_gather(const int* __restrict__ word_ids) {
    int w = threadIdx.x >> 5, lane = threadIdx.x & 31;
    int b = blockIdx.x * 8 + w;
    int idv = 0;
    if (lane < NGW) idv = word_ids[b * NGW + lane];
    float4 a0 = make_float4(0, 0, 0, 0), a1 = a0, a2 = a0;
    #pragma unroll
    for (int g = 0; g < NGW; g++) {
        int id = __shfl_sync(0xffffffffu, idv, g);
        const float4* row = (const float4*)&d_rvT[(size_t)id * RVLD];
        float4 v0 = row[lane];
        float4 v1 = row[lane + 32];
        a0.x += v0.x; a0.y += v0.y; a0.z += v0.z; a0.w += v0.w;
        a1.x += v1.x; a1.y += v1.y; a1.z += v1.z; a1.w += v1.w;
        if (lane < 16) {
            float4 v2 = row[lane + 64];
            a2.x += v2.x; a2.y += v2.y; a2.z += v2.z; a2.w += v2.w;
        }
    }
    float ss = a0.x * a0.x + a0.y * a0.y + a0.z * a0.z + a0.w * a0.w
             + a1.x * a1.x + a1.y * a1.y + a1.z * a1.z + a1.w * a1.w
             + a2.x * a2.x + a2.y * a2.y + a2.z * a2.z + a2.w * a2.w;
    ss = warp_sum(ss);
    float rn = 1.f / sqrtf(ss);
    float4* outp = (float4*)&d_normedT[(size_t)b * KP];
    a0.x *= rn; a0.y *= rn; a0.z *= rn; a0.w *= rn;
    a1.x *= rn; a1.y *= rn; a1.z *= rn; a1.w *= rn;
    outp[lane] = a0;
    outp[lane + 32] = a1;
    if (lane < 16) {
        a2.x *= rn; a2.y *= rn; a2.z *= rn; a2.w *= rn;
        outp[lane + 64] = a2;
    }
}

// ---- K5: GEMM 4096x256x320 with fused per-de Σ/Σ² ----
__global__ __launch_bounds__(256) void k_gemm() {
    __shared__ float As[BM][BK + 1];
    __shared__ float Bs[BN][BK + 1];
    int tid = threadIdx.x;
    int tx = tid & 15, ty = tid >> 4;
    int b0 = blockIdx.x * BM;
    int d0 = blockIdx.y * BN;
    float acc[4][4];
    #pragma unroll
    for (int i = 0; i < 4; i++)
        #pragma unroll
        for (int j = 0; j < 4; j++) acc[i][j] = 0.f;

    for (int k0 = 0; k0 < KP; k0 += BK) {
        #pragma unroll
        for (int l = 0; l < 2; l++) {
            int f = tid + l * 256;
            int r = f >> 3, c = (f & 7) << 2;
            float4 va = *(const float4*)&d_normedT[(size_t)(b0 + r) * KP + k0 + c];
            As[r][c] = va.x; As[r][c+1] = va.y; As[r][c+2] = va.z; As[r][c+3] = va.w;
            float4 vb = *(const float4*)&d_projP[(size_t)(d0 + r) * KP + k0 + c];
            Bs[r][c] = vb.x; Bs[r][c+1] = vb.y; Bs[r][c+2] = vb.z; Bs[r][c+3] = vb.w;
        }
        __syncthreads();
        #pragma unroll
        for (int k = 0; k < BK; k++) {
            float a[4], bb[4];
            #pragma unroll
            for (int i = 0; i < 4; i++) a[i] = As[ty * 4 + i][k];
            #pragma unroll
            for (int j = 0; j < 4; j++) bb[j] = Bs[tx * 4 + j][k];
            #pragma unroll
            for (int i = 0; i < 4; i++)
                #pragma unroll
                for (int j = 0; j < 4; j++) acc[i][j] += a[i] * bb[j];
        }
        __syncthreads();
    }

    #pragma unroll
    for (int i = 0; i < 4; i++) {
        float4 o = make_float4(acc[i][0], acc[i][1], acc[i][2], acc[i][3]);
        *(float4*)&d_tpreT[(size_t)(b0 + ty * 4 + i) * DE + d0 + tx * 4] = o;
    }

    __shared__ float stS[16][64];
    __shared__ float stQ[16][64];
    #pragma unroll
    for (int j = 0; j < 4; j++) {
        float s = 0.f, q = 0.f;
        #pragma unroll
        for (int i = 0; i < 4; i++) { s += acc[i][j]; q += acc[i][j] * acc[i][j]; }
        stS[ty][tx * 4 + j] = s;
        stQ[ty][tx * 4 + j] = q;
    }
    __syncthreads();
    if (tid < 64) {
        float s = 0.f, q = 0.f;
        #pragma unroll
        for (int r = 0; r < 16; r++) { s += stS[r][tid]; q += stQ[r][tid]; }
        atomicAdd(&d_sum[d0 + tid], (double)s);
        atomicAdd(&d_sumsq[d0 + tid], (double)q);
    }
}

// ---- K6: finalize per-de affine (tiny; FP64 fine here) ----
__global__ void k_stats(const float* __restrict__ beta) {
    int de = threadIdx.x;
    double s = d_sum[de], q = d_sumsq[de];
    double mean = s / NB;
    double var = (q - s * mean) / (NB - 1);   // ddof = 1
    if (var < 1e-30) var = 1e-30;
    double rs = 1.0 / sqrt(sqrt(var));        // 1/sqrt(std)
    d_ca[de] = (float)rs;
    d_cb[de] = (float)((double)beta[de] - mean * rs);
    if (de == 0) {
        double p = 0.0;
        for (int i = 0; i < 64; i++) p += (double)d_projpart[i];
        d_projsq = p;
    }
}

// ---- K7: loss — 256 threads; warps 0-7 do dots 0-7, warps 5-7 redo 8-10 ----
__global__ __launch_bounds__(256) void k_loss(const int* __restrict__ doc_ids,
                                              const int* __restrict__ neg_ids,
                                              float* __restrict__ out) {
    int b = blockIdx.x, tid = threadIdx.x;
    int w = tid >> 5, lane = tid & 31;
    __shared__ float ts[DE];
    __shared__ float dots[11];
    __shared__ int   ids[11];
    if (tid < 11) ids[tid] = (tid == 0) ? doc_ids[b] : neg_ids[b * NZ + tid - 1];
    {
        float t = d_tpreT[(size_t)b * DE + tid] * d_ca[tid] + d_cb[tid];
        ts[tid] = fminf(1.f, fmaxf(-1.f, t));
    }
    __syncthreads();

    const float4* tt = (const float4*)ts;
    float4 t0 = tt[lane], t1 = tt[lane + 32];

    // pass 1: dots 0..7 on warps 0..7
    {
        int id = ids[w];
        const float4* rr = (const float4*)&d_rdT[(size_t)id * DE];
        float4 r0 = rr[lane], r1 = rr[lane + 32];
        float v = t0.x * r0.x + t0.y * r0.y + t0.z * r0.z + t0.w * r0.w
                + t1.x * r1.x + t1.y * r1.y + t1.z * r1.z + t1.w * r1.w;
        v = warp_sum(v);
        if (!lane) dots[w] = v;
    }
    // pass 2: dots 8..10 on warps 5..7
    if (w >= 5) {
        int id = ids[w + 3];
        const float4* rr = (const float4*)&d_rdT[(size_t)id * DE];
        float4 r0 = rr[lane], r1 = rr[lane + 32];
        float v = t0.x * r0.x + t0.y * r0.y + t0.z * r0.z + t0.w * r0.w
                + t1.x * r1.x + t1.y * r1.y + t1.z * r1.z + t1.w * r1.w;
        v = warp_sum(v);
        if (!lane) dots[w + 3] = v;
    }
    __syncthreads();
    if (tid == 0) {
        float p  = fminf(1.f / (1.f + expf(-dots[0])), 0.999f);
        float lp = 10.f * logf(p);
        float nsl = 0.f;
        #pragma unroll
        for (int z = 1; z <= NZ; z++) {
            float pn = fminf(1.f / (1.f + expf(-dots[z])), 0.999f);
            nsl += logf(fmaxf(1.f - pn, 0.01f));
        }
        atomicAdd(&d_loss, (double)(0.55f * (lp + nsl)));   // (Z+1)/(2Z)
        __threadfence();
        unsigned int r = atomicAdd(&d_count, 1u);
        if (r == NB - 1) {
            double total = atomicAdd(&d_loss, 0.0);
            out[0] = (float)(total / NB + (0.01 / (2.0 * NB)) * (d_rdsq + d_projsq));
        }
    }
}

extern "C" void kernel_launch(void* const* d_in, const int* in_sizes, int n_in,
                              void* d_out, int out_size) {
    const float* rv       = (const float*)d_in[0];
    const float* rd       = (const float*)d_in[1];
    const float* proj     = (const float*)d_in[2];
    const float* beta     = (const float*)d_in[3];
    const int*   word_ids = (const int*)d_in[4];
    const int*   doc_ids  = (const int*)d_in[5];
    const int*   neg_ids  = (const int*)d_in[6];
    float* out = (float*)d_out;

    k_init<<<1, 512>>>();
    k_rv_T<<<dim3((NV + 63) / 64, 5), 256>>>(rv);       // rvT L2-hot for gather
    k_proj_prep<<<64, 256>>>(proj);
    k_gather<<<NB / 8, 256>>>(word_ids);
    k_gemm<<<dim3(NB / BM, DE / BN), 256>>>();
    k_stats<<<1, DE>>>(beta);
    k_rd_T<<<dim3((ND + 63) / 64, DE / 64), 256>>>(rd); // rdT L2-hot for loss
    k_loss<<<NB, 256>>>(doc_ids, neg_ids, out);
}

// round 6
// speedup vs baseline: 1.6301x; 1.1313x over previous
#include <cuda_runtime.h>
#include <math.h>

// Problem constants
#define WE    300      // word-embedding dim
#define RVLD  320      // padded row length for rvT (1280B, 128-aligned)
#define DE    256      // doc-embedding dim
#define NV    50000    // vocab
#define ND    100000   // docs
#define NB    4096     // batch
#define NGW   10       // words per bag
#define NZ    10       // negatives
#define KP    320      // padded K for GEMM

#define BM 64
#define BN 64
#define BK 32

// ---- device scratch (zero-initialized at module load; k_loss restores zeros) ----
__device__ float  d_rvT[NV * RVLD];        // 64 MB
__device__ float  d_rdT[ND * DE];          // 102 MB
__device__ float  d_normedT[NB * KP];      // 5 MB
__device__ float  d_projP[DE * KP];        // 0.3 MB
__device__ float  d_tpreT[NB * DE];        // 4 MB
__device__ float  d_projpart[64];
__device__ double d_sum[DE];
__device__ double d_sumsq[DE];
__device__ double d_rdsq;
__device__ double d_projsq;
__device__ double d_loss;
__device__ unsigned int d_count;
__device__ float  d_ca[DE];
__device__ float  d_cb[DE];

__device__ __forceinline__ float warp_sum(float v) {
    #pragma unroll
    for (int o = 16; o > 0; o >>= 1) v += __shfl_xor_sync(0xffffffffu, v, o);
    return v;
}

// ---- K1: transpose rd -> rdT, fused sum(rd^2); block(0,0) also finalizes stats ----
__global__ __launch_bounds__(256) void k_rd_T(const float* __restrict__ rd,
                                              const float* __restrict__ beta) {
    // stats finalize (was k_stats): runs after k_gemm in stream order
    if (blockIdx.x == 0 && blockIdx.y == 0) {
        int de = threadIdx.x;
        double s = d_sum[de], q = d_sumsq[de];
        double mean = s / NB;
        double var = (q - s * mean) / (NB - 1);   // ddof = 1
        if (var < 1e-30) var = 1e-30;
        double rs = 1.0 / sqrt(sqrt(var));        // 1/sqrt(std)
        d_ca[de] = (float)rs;
        d_cb[de] = (float)((double)beta[de] - mean * rs);
        if (de == 0) {
            double p = 0.0;
            for (int i = 0; i < 64; i++) p += (double)d_projpart[i];
            d_projsq = p;
        }
    }

    __shared__ float tile[64][65];
    int t = threadIdx.x;
    int x0 = blockIdx.x * 64;          // doc
    int y0 = blockIdx.y * 64;          // de
    int r = t >> 4;                    // 0..15
    int c = (t & 15) << 2;             // 0,4,..,60
    float ss = 0.f;
    #pragma unroll
    for (int i = 0; i < 4; i++) {
        int de = r + 16 * i;
        int doc = x0 + c;
        if (doc < ND) {
            float4 v = *(const float4*)&rd[(size_t)(y0 + de) * ND + doc];
            tile[de][c] = v.x; tile[de][c + 1] = v.y;
            tile[de][c + 2] = v.z; tile[de][c + 3] = v.w;
            ss += v.x * v.x + v.y * v.y + v.z * v.z + v.w * v.w;
        }
    }
    __syncthreads();
    #pragma unroll
    for (int i = 0; i < 4; i++) {
        int dl = r + 16 * i;           // doc local
        int doc = x0 + dl;
        if (doc < ND) {
            float4 o = make_float4(tile[c][dl], tile[c + 1][dl],
                                   tile[c + 2][dl], tile[c + 3][dl]);
            *(float4*)&d_rdT[(size_t)doc * DE + y0 + c] = o;
        }
    }
    ss = warp_sum(ss);
    __shared__ float red[8];
    if ((t & 31) == 0) red[t >> 5] = ss;
    __syncthreads();
    if (t == 0) {
        float s = 0.f;
        #pragma unroll
        for (int i = 0; i < 8; i++) s += red[i];
        atomicAdd(&d_rdsq, (double)s);
    }
}

// ---- K2: transpose rv (300 x 50000) -> rvT (50000 x 320, zero-padded) ----
__global__ __launch_bounds__(256) void k_rv_T(const float* __restrict__ rv) {
    __shared__ float tile[64][65];
    int t = threadIdx.x;
    int x0 = blockIdx.x * 64;          // v
    int y0 = blockIdx.y * 64;          // we
    int r = t >> 4;
    int c = (t & 15) << 2;
    #pragma unroll
    for (int i = 0; i < 4; i++) {
        int we = y0 + r + 16 * i;
        int x = x0 + c;
        if (x < NV) {
            float4 v = make_float4(0.f, 0.f, 0.f, 0.f);
            if (we < WE) v = *(const float4*)&rv[(size_t)we * NV + x];
            int de = r + 16 * i;
            tile[de][c] = v.x; tile[de][c + 1] = v.y;
            tile[de][c + 2] = v.z; tile[de][c + 3] = v.w;
        }
    }
    __syncthreads();
    #pragma unroll
    for (int i = 0; i < 4; i++) {
        int vl = r + 16 * i;
        int v = x0 + vl;
        if (v < NV) {
            float4 o = make_float4(tile[c][vl], tile[c + 1][vl],
                                   tile[c + 2][vl], tile[c + 3][vl]);
            *(float4*)&d_rvT[(size_t)v * RVLD + y0 + c] = o;
        }
    }
}

// ---- K3: pad proj into projP, per-block partial sum(proj^2) ----
__global__ __launch_bounds__(256) void k_proj_prep(const float* __restrict__ proj) {
    int idx = blockIdx.x * 256 + threadIdx.x;
    float ss = 0.f;
    #pragma unroll
    for (int i = 0; i < 5; i++) {
        int o = idx + i * 64 * 256;
        int de = o / KP, cc = o % KP;
        float v = 0.f;
        if (cc < WE) { v = proj[de * WE + cc]; ss += v * v; }
        d_projP[o] = v;
    }
    ss = warp_sum(ss);
    __shared__ float red[8];
    int t = threadIdx.x;
    if ((t & 31) == 0) red[t >> 5] = ss;
    __syncthreads();
    if (t == 0) {
        float s = 0.f;
        #pragma unroll
        for (int i = 0; i < 8; i++) s += red[i];
        d_projpart[blockIdx.x] = s;
    }
}

// ---- K4: gather+normalize, 2 warps per batch (grid 1024), float4 ----
__global__ __launch_bounds__(256) void k_gather(const int* __restrict__ word_ids) {
    int tid = threadIdx.x;
    int pw   = tid >> 6;               // batch-pair slot 0..3
    int half = (tid >> 5) & 1;         // which half of the 80 float4 chunks
    int w    = tid >> 5;               // warp id 0..7
    int lane = tid & 31;
    int b = blockIdx.x * 4 + pw;

    int idv = 0;
    if (lane < NGW) idv = word_ids[b * NGW + lane];

    int c0 = half * 40 + lane;         // chunk 0..79 (float4 index in 320-float row)
    int c1 = c0 + 32;                  // only lanes 0..7 (c1 < half*40+40)
    bool has1 = (lane < 8);

    float4 a0 = make_float4(0, 0, 0, 0), a1 = a0;
    #pragma unroll
    for (int g = 0; g < NGW; g++) {
        int id = __shfl_sync(0xffffffffu, idv, g);
        const float4* row = (const float4*)&d_rvT[(size_t)id * RVLD];
        float4 v0 = row[c0];
        a0.x += v0.x; a0.y += v0.y; a0.z += v0.z; a0.w += v0.w;
        if (has1) {
            float4 v1 = row[c1];
            a1.x += v1.x; a1.y += v1.y; a1.z += v1.z; a1.w += v1.w;
        }
    }
    float ss = a0.x * a0.x + a0.y * a0.y + a0.z * a0.z + a0.w * a0.w
             + a1.x * a1.x + a1.y * a1.y + a1.z * a1.z + a1.w * a1.w;
    ss = warp_sum(ss);
    __shared__ float pss[8];
    if (!lane) pss[w] = ss;
    __syncthreads();
    float rn = rsqrtf(pss[pw * 2] + pss[pw * 2 + 1]);

    float4* outp = (float4*)&d_normedT[(size_t)b * KP];
    a0.x *= rn; a0.y *= rn; a0.z *= rn; a0.w *= rn;
    outp[c0] = a0;
    if (has1) {
        a1.x *= rn; a1.y *= rn; a1.z *= rn; a1.w *= rn;
        outp[c1] = a1;
    }
}

// ---- K5: GEMM 4096x256x320 with fused per-de Σ/Σ² ----
__global__ __launch_bounds__(256) void k_gemm() {
    __shared__ float As[BM][BK + 1];
    __shared__ float Bs[BN][BK + 1];
    int tid = threadIdx.x;
    int tx = tid & 15, ty = tid >> 4;
    int b0 = blockIdx.x * BM;
    int d0 = blockIdx.y * BN;
    float acc[4][4];
    #pragma unroll
    for (int i = 0; i < 4; i++)
        #pragma unroll
        for (int j = 0; j < 4; j++) acc[i][j] = 0.f;

    for (int k0 = 0; k0 < KP; k0 += BK) {
        #pragma unroll
        for (int l = 0; l < 2; l++) {
            int f = tid + l * 256;
            int r = f >> 3, c = (f & 7) << 2;
            float4 va = *(const float4*)&d_normedT[(size_t)(b0 + r) * KP + k0 + c];
            As[r][c] = va.x; As[r][c+1] = va.y; As[r][c+2] = va.z; As[r][c+3] = va.w;
            float4 vb = *(const float4*)&d_projP[(size_t)(d0 + r) * KP + k0 + c];
            Bs[r][c] = vb.x; Bs[r][c+1] = vb.y; Bs[r][c+2] = vb.z; Bs[r][c+3] = vb.w;
        }
        __syncthreads();
        #pragma unroll
        for (int k = 0; k < BK; k++) {
            float a[4], bb[4];
            #pragma unroll
            for (int i = 0; i < 4; i++) a[i] = As[ty * 4 + i][k];
            #pragma unroll
            for (int j = 0; j < 4; j++) bb[j] = Bs[tx * 4 + j][k];
            #pragma unroll
            for (int i = 0; i < 4; i++)
                #pragma unroll
                for (int j = 0; j < 4; j++) acc[i][j] += a[i] * bb[j];
        }
        __syncthreads();
    }

    #pragma unroll
    for (int i = 0; i < 4; i++) {
        float4 o = make_float4(acc[i][0], acc[i][1], acc[i][2], acc[i][3]);
        *(float4*)&d_tpreT[(size_t)(b0 + ty * 4 + i) * DE + d0 + tx * 4] = o;
    }

    __shared__ float stS[16][64];
    __shared__ float stQ[16][64];
    #pragma unroll
    for (int j = 0; j < 4; j++) {
        float s = 0.f, q = 0.f;
        #pragma unroll
        for (int i = 0; i < 4; i++) { s += acc[i][j]; q += acc[i][j] * acc[i][j]; }
        stS[ty][tx * 4 + j] = s;
        stQ[ty][tx * 4 + j] = q;
    }
    __syncthreads();
    if (tid < 64) {
        float s = 0.f, q = 0.f;
        #pragma unroll
        for (int r = 0; r < 16; r++) { s += stS[r][tid]; q += stQ[r][tid]; }
        atomicAdd(&d_sum[d0 + tid], (double)s);
        atomicAdd(&d_sumsq[d0 + tid], (double)q);
    }
}

// ---- K6: loss; last block finalizes output and re-zeros accumulator state ----
__global__ __launch_bounds__(256) void k_loss(const int* __restrict__ doc_ids,
                                              const int* __restrict__ neg_ids,
                                              float* __restrict__ out) {
    int b = blockIdx.x, tid = threadIdx.x;
    int w = tid >> 5, lane = tid & 31;
    __shared__ float ts[DE];
    __shared__ float dots[11];
    __shared__ int   ids[11];
    if (tid < 11) ids[tid] = (tid == 0) ? doc_ids[b] : neg_ids[b * NZ + tid - 1];
    {
        float t = d_tpreT[(size_t)b * DE + tid] * d_ca[tid] + d_cb[tid];
        ts[tid] = fminf(1.f, fmaxf(-1.f, t));
    }
    __syncthreads();

    const float4* tt = (const float4*)ts;
    float4 t0 = tt[lane], t1 = tt[lane + 32];

    // pass 1: dots 0..7 on warps 0..7
    {
        int id = ids[w];
        const float4* rr = (const float4*)&d_rdT[(size_t)id * DE];
        float4 r0 = rr[lane], r1 = rr[lane + 32];
        float v = t0.x * r0.x + t0.y * r0.y + t0.z * r0.z + t0.w * r0.w
                + t1.x * r1.x + t1.y * r1.y + t1.z * r1.z + t1.w * r1.w;
        v = warp_sum(v);
        if (!lane) dots[w] = v;
    }
    // pass 2: dots 8..10 on warps 5..7
    if (w >= 5) {
        int id = ids[w + 3];
        const float4* rr = (const float4*)&d_rdT[(size_t)id * DE];
        float4 r0 = rr[lane], r1 = rr[lane + 32];
        float v = t0.x * r0.x + t0.y * r0.y + t0.z * r0.z + t0.w * r0.w
                + t1.x * r1.x + t1.y * r1.y + t1.z * r1.z + t1.w * r1.w;
        v = warp_sum(v);
        if (!lane) dots[w + 3] = v;
    }
    __syncthreads();
    if (tid == 0) {
        float p  = fminf(1.f / (1.f + expf(-dots[0])), 0.999f);
        float lp = 10.f * logf(p);
        float nsl = 0.f;
        #pragma unroll
        for (int z = 1; z <= NZ; z++) {
            float pn = fminf(1.f / (1.f + expf(-dots[z])), 0.999f);
            nsl += logf(fmaxf(1.f - pn, 0.01f));
        }
        atomicAdd(&d_loss, (double)(0.55f * (lp + nsl)));   // (Z+1)/(2Z)
        __threadfence();
        unsigned int r = atomicAdd(&d_count, 1u);
        if (r == NB - 1) {
            // all blocks' contributions are visible; finalize
            double total = atomicAdd(&d_loss, 0.0);
            out[0] = (float)(total / NB + (0.01 / (2.0 * NB)) * (d_rdsq + d_projsq));
            // restore zero-state for the next graph replay (deterministic)
            for (int i = 0; i < DE; i++) { d_sum[i] = 0.0; d_sumsq[i] = 0.0; }
            d_loss = 0.0;
            d_rdsq = 0.0;
            __threadfence();
            d_count = 0u;
        }
    }
}

extern "C" void kernel_launch(void* const* d_in, const int* in_sizes, int n_in,
                              void* d_out, int out_size) {
    const float* rv       = (const float*)d_in[0];
    const float* rd       = (const float*)d_in[1];
    const float* proj     = (const float*)d_in[2];
    const float* beta     = (const float*)d_in[3];
    const int*   word_ids = (const int*)d_in[4];
    const int*   doc_ids  = (const int*)d_in[5];
    const int*   neg_ids  = (const int*)d_in[6];
    float* out = (float*)d_out;

    k_rv_T<<<dim3((NV + 63) / 64, 5), 256>>>(rv);        // rvT L2-hot for gather
    k_proj_prep<<<64, 256>>>(proj);
    k_gather<<<NB / 4, 256>>>(word_ids);
    k_gemm<<<dim3(NB / BM, DE / BN), 256>>>();
    k_rd_T<<<dim3((ND + 63) / 64, DE / 64), 256>>>(rd, beta);  // + stats finalize
    k_loss<<<NB, 256>>>(doc_ids, neg_ids, out);
}